// round 1
// baseline (speedup 1.0000x reference)
#include <cuda_runtime.h>
#include <cstdint>

#define D 64
#define NODE_STRIDE 256   // 4 layers * 64 floats, node-major [n][4][64]

// ---------------------------------------------------------------------------
// Kernel 1: embs[:,0,:] = concat(user_emb, item_emb); embs[:,1..3,:] = 0
// One thread per float4 of the d=64 row (16 float4s per node).
// ---------------------------------------------------------------------------
__global__ void lgcn_init_kernel(const float* __restrict__ user_emb,
                                 const float* __restrict__ item_emb,
                                 float* __restrict__ embs,
                                 int n_users, int n) {
    int idx = blockIdx.x * blockDim.x + threadIdx.x;
    int total = n * (D / 4);
    if (idx >= total) return;
    int node = idx >> 4;
    int q    = idx & 15;

    const float4* src = (node < n_users)
        ? reinterpret_cast<const float4*>(user_emb + (size_t)node * D)
        : reinterpret_cast<const float4*>(item_emb + (size_t)(node - n_users) * D);
    float4 v = src[q];

    float4* base = reinterpret_cast<float4*>(embs + (size_t)node * NODE_STRIDE);
    float4 z = make_float4(0.f, 0.f, 0.f, 0.f);
    base[q]      = v;   // layer 0
    base[16 + q] = z;   // layer 1 (atomic target — must be re-zeroed each replay)
    base[32 + q] = z;   // layer 2
    base[48 + q] = z;   // layer 3
}

// ---------------------------------------------------------------------------
// Kernel 2: SpMM scatter-gather. y[row] += val * x[col].
// 16 threads per edge, one float4 each (256B row fully coalesced).
// Vector red.global.add.v4.f32 quarters the L2 atomic op count.
// ---------------------------------------------------------------------------
__global__ void lgcn_spmm_kernel(const int*   __restrict__ edge_row,
                                 const int*   __restrict__ edge_col,
                                 const float* __restrict__ edge_val,
                                 const float* __restrict__ x_base,  // embs + (l-1)*64
                                 float*       __restrict__ y_base,  // embs + l*64
                                 int n_edges) {
    long long t = (long long)blockIdx.x * blockDim.x + threadIdx.x;
    int e = (int)(t >> 4);
    if (e >= n_edges) return;
    int q = (int)(t & 15);

    int   r = edge_row[e];
    int   c = edge_col[e];
    float w = edge_val[e];

    const float4* xs = reinterpret_cast<const float4*>(x_base + (size_t)c * NODE_STRIDE);
    float4 v = xs[q];

    float* dst = y_base + (size_t)r * NODE_STRIDE + q * 4;
    asm volatile("red.global.add.v4.f32 [%0], {%1, %2, %3, %4};"
                 :: "l"(dst), "f"(v.x * w), "f"(v.y * w), "f"(v.z * w), "f"(v.w * w)
                 : "memory");
}

// ---------------------------------------------------------------------------
// Kernel 3: light_out = mean(embs over layer axis); split into users/items.
// ---------------------------------------------------------------------------
__global__ void lgcn_mean_kernel(const float* __restrict__ embs,
                                 float* __restrict__ users,
                                 float* __restrict__ items,
                                 int n_users, int n) {
    int idx = blockIdx.x * blockDim.x + threadIdx.x;
    int total = n * (D / 4);
    if (idx >= total) return;
    int node = idx >> 4;
    int q    = idx & 15;

    const float4* base = reinterpret_cast<const float4*>(embs + (size_t)node * NODE_STRIDE);
    float4 a0 = base[q];
    float4 a1 = base[16 + q];
    float4 a2 = base[32 + q];
    float4 a3 = base[48 + q];

    float4 m = make_float4((a0.x + a1.x + a2.x + a3.x) * 0.25f,
                           (a0.y + a1.y + a2.y + a3.y) * 0.25f,
                           (a0.z + a1.z + a2.z + a3.z) * 0.25f,
                           (a0.w + a1.w + a2.w + a3.w) * 0.25f);

    float4* dst = (node < n_users)
        ? reinterpret_cast<float4*>(users + (size_t)node * D)
        : reinterpret_cast<float4*>(items + (size_t)(node - n_users) * D);
    dst[q] = m;
}

// ---------------------------------------------------------------------------
// Launch: out layout = [users (n_users*64)] [items (n_items*64)] [embs (n*4*64)]
// ---------------------------------------------------------------------------
extern "C" void kernel_launch(void* const* d_in, const int* in_sizes, int n_in,
                              void* d_out, int out_size) {
    const float* user_emb = (const float*)d_in[0];
    const float* item_emb = (const float*)d_in[1];
    const int*   edge_row = (const int*)d_in[2];
    const int*   edge_col = (const int*)d_in[3];
    const float* edge_val = (const float*)d_in[4];

    int n_users = in_sizes[0] / D;
    int n_items = in_sizes[1] / D;
    int n       = n_users + n_items;
    int n_edges = in_sizes[2];

    float* out   = (float*)d_out;
    float* users = out;
    float* items = out + (size_t)n_users * D;
    float* embs  = out + (size_t)n * D;   // [n][4][64]

    const int TPB = 256;

    // init: layer 0 + zero layers 1..3
    {
        int total = n * (D / 4);
        lgcn_init_kernel<<<(total + TPB - 1) / TPB, TPB>>>(user_emb, item_emb, embs,
                                                           n_users, n);
    }

    // 3 SpMM layers: layer l reads embs[:,l-1,:], scatters into embs[:,l,:]
    {
        long long threads = (long long)n_edges * 16;
        int grid = (int)((threads + TPB - 1) / TPB);
        for (int l = 1; l <= 3; ++l) {
            lgcn_spmm_kernel<<<grid, TPB>>>(edge_row, edge_col, edge_val,
                                            embs + (size_t)(l - 1) * D,
                                            embs + (size_t)l * D,
                                            n_edges);
        }
    }

    // mean over layers -> users / items
    {
        int total = n * (D / 4);
        lgcn_mean_kernel<<<(total + TPB - 1) / TPB, TPB>>>(embs, users, items,
                                                           n_users, n);
    }
}

// round 2
// speedup vs baseline: 1.6969x; 1.6969x over previous
#include <cuda_runtime.h>
#include <cstdint>

#define D 64
#define NODE_STRIDE 256        // 4 layers * 64 floats, node-major [n][4][64]
#define MAX_NODES   150016
#define MAX_EDGES   3000000
#define SCAN_BS     512

// ---------------------------------------------------------------------------
// Static scratch (allocation-free rule: __device__ globals)
// ---------------------------------------------------------------------------
__device__ int  d_cnt[MAX_NODES];
__device__ int  d_row_ptr[MAX_NODES + 1];
__device__ int  d_cursor[MAX_NODES];
__device__ int  d_bsums[SCAN_BS];
__device__ int2 d_edges_sorted[MAX_EDGES];   // (col, val bits), grouped by row

// ---------------------------------------------------------------------------
// CSR build
// ---------------------------------------------------------------------------
__global__ void lgcn_zero_cnt(int n) {
    int i = blockIdx.x * blockDim.x + threadIdx.x;
    if (i < n) d_cnt[i] = 0;
}

__global__ void lgcn_hist(const int* __restrict__ edge_row, int n_edges) {
    int e = blockIdx.x * blockDim.x + threadIdx.x;
    if (e < n_edges) atomicAdd(&d_cnt[edge_row[e]], 1);
}

// Block-wise exclusive scan of d_cnt -> d_row_ptr (partial), block totals -> d_bsums
__global__ void lgcn_scan_blocks(int n) {
    __shared__ int s[SCAN_BS];
    int t = threadIdx.x;
    int i = blockIdx.x * SCAN_BS + t;
    int v = (i < n) ? d_cnt[i] : 0;
    s[t] = v;
    __syncthreads();
    #pragma unroll
    for (int off = 1; off < SCAN_BS; off <<= 1) {
        int tmp = (t >= off) ? s[t - off] : 0;
        __syncthreads();
        s[t] += tmp;
        __syncthreads();
    }
    if (i < n) d_row_ptr[i] = s[t] - v;      // exclusive
    if (t == SCAN_BS - 1) d_bsums[blockIdx.x] = s[t];
}

// Single-block exclusive scan of block sums (nb <= SCAN_BS)
__global__ void lgcn_scan_sums(int nb) {
    __shared__ int s[SCAN_BS];
    int t = threadIdx.x;
    int v = (t < nb) ? d_bsums[t] : 0;
    s[t] = v;
    __syncthreads();
    #pragma unroll
    for (int off = 1; off < SCAN_BS; off <<= 1) {
        int tmp = (t >= off) ? s[t - off] : 0;
        __syncthreads();
        s[t] += tmp;
        __syncthreads();
    }
    if (t < nb) d_bsums[t] = s[t] - v;       // exclusive
}

// Add block offsets; copy to cursor; cap row_ptr with n_edges
__global__ void lgcn_scan_add(int n, int n_edges) {
    int i = blockIdx.x * blockDim.x + threadIdx.x;
    if (i < n) {
        int p = d_row_ptr[i] + d_bsums[i / SCAN_BS];
        d_row_ptr[i] = p;
        d_cursor[i]  = p;
    }
    if (i == 0) d_row_ptr[n] = n_edges;
}

__global__ void lgcn_scatter(const int*   __restrict__ edge_row,
                             const int*   __restrict__ edge_col,
                             const float* __restrict__ edge_val,
                             int n_edges) {
    int e = blockIdx.x * blockDim.x + threadIdx.x;
    if (e >= n_edges) return;
    int r = edge_row[e];
    int p = atomicAdd(&d_cursor[r], 1);
    d_edges_sorted[p] = make_int2(edge_col[e], __float_as_int(edge_val[e]));
}

// ---------------------------------------------------------------------------
// embs[:,0,:] = concat(user_emb, item_emb)   (layers 1..3 fully written by spmm)
// ---------------------------------------------------------------------------
__global__ void lgcn_init_kernel(const float* __restrict__ user_emb,
                                 const float* __restrict__ item_emb,
                                 float* __restrict__ embs,
                                 int n_users, int n) {
    int idx = blockIdx.x * blockDim.x + threadIdx.x;
    int total = n * (D / 4);
    if (idx >= total) return;
    int node = idx >> 4;
    int q    = idx & 15;
    const float4* src = (node < n_users)
        ? reinterpret_cast<const float4*>(user_emb + (size_t)node * D)
        : reinterpret_cast<const float4*>(item_emb + (size_t)(node - n_users) * D);
    reinterpret_cast<float4*>(embs + (size_t)node * NODE_STRIDE)[q] = src[q];
}

// ---------------------------------------------------------------------------
// SpMM, CSR, warp-per-row, no atomics.
// Lane holds float2 of the 64-float row. Unroll-2 over edges for MLP.
// ---------------------------------------------------------------------------
__global__ void lgcn_spmm_csr(const float* __restrict__ x_base,  // embs + (l-1)*64
                              float*       __restrict__ y_base,  // embs + l*64
                              int n) {
    int warp = (blockIdx.x * blockDim.x + threadIdx.x) >> 5;
    int lane = threadIdx.x & 31;
    if (warp >= n) return;

    int start = d_row_ptr[warp];
    int end   = d_row_ptr[warp + 1];

    float ax = 0.f, ay = 0.f, bx = 0.f, by = 0.f;

    int e = start;
    for (; e + 1 < end; e += 2) {
        int2 m0 = d_edges_sorted[e];
        int2 m1 = d_edges_sorted[e + 1];
        float w0 = __int_as_float(m0.y);
        float w1 = __int_as_float(m1.y);
        float2 v0 = reinterpret_cast<const float2*>(x_base + (size_t)m0.x * NODE_STRIDE)[lane];
        float2 v1 = reinterpret_cast<const float2*>(x_base + (size_t)m1.x * NODE_STRIDE)[lane];
        ax += w0 * v0.x;  ay += w0 * v0.y;
        bx += w1 * v1.x;  by += w1 * v1.y;
    }
    if (e < end) {
        int2 m0 = d_edges_sorted[e];
        float w0 = __int_as_float(m0.y);
        float2 v0 = reinterpret_cast<const float2*>(x_base + (size_t)m0.x * NODE_STRIDE)[lane];
        ax += w0 * v0.x;  ay += w0 * v0.y;
    }

    reinterpret_cast<float2*>(y_base + (size_t)warp * NODE_STRIDE)[lane] =
        make_float2(ax + bx, ay + by);
}

// ---------------------------------------------------------------------------
// light_out = mean over layer axis; split into users/items.
// ---------------------------------------------------------------------------
__global__ void lgcn_mean_kernel(const float* __restrict__ embs,
                                 float* __restrict__ users,
                                 float* __restrict__ items,
                                 int n_users, int n) {
    int idx = blockIdx.x * blockDim.x + threadIdx.x;
    int total = n * (D / 4);
    if (idx >= total) return;
    int node = idx >> 4;
    int q    = idx & 15;

    const float4* base = reinterpret_cast<const float4*>(embs + (size_t)node * NODE_STRIDE);
    float4 a0 = base[q];
    float4 a1 = base[16 + q];
    float4 a2 = base[32 + q];
    float4 a3 = base[48 + q];

    float4 m = make_float4((a0.x + a1.x + a2.x + a3.x) * 0.25f,
                           (a0.y + a1.y + a2.y + a3.y) * 0.25f,
                           (a0.z + a1.z + a2.z + a3.z) * 0.25f,
                           (a0.w + a1.w + a2.w + a3.w) * 0.25f);

    float4* dst = (node < n_users)
        ? reinterpret_cast<float4*>(users + (size_t)node * D)
        : reinterpret_cast<float4*>(items + (size_t)(node - n_users) * D);
    dst[q] = m;
}

// ---------------------------------------------------------------------------
// out layout = [users (n_users*64)] [items (n_items*64)] [embs (n*4*64)]
// ---------------------------------------------------------------------------
extern "C" void kernel_launch(void* const* d_in, const int* in_sizes, int n_in,
                              void* d_out, int out_size) {
    const float* user_emb = (const float*)d_in[0];
    const float* item_emb = (const float*)d_in[1];
    const int*   edge_row = (const int*)d_in[2];
    const int*   edge_col = (const int*)d_in[3];
    const float* edge_val = (const float*)d_in[4];

    int n_users = in_sizes[0] / D;
    int n_items = in_sizes[1] / D;
    int n       = n_users + n_items;
    int n_edges = in_sizes[2];

    float* out   = (float*)d_out;
    float* users = out;
    float* items = out + (size_t)n_users * D;
    float* embs  = out + (size_t)n * D;   // [n][4][64]

    const int TPB = 256;
    int nb = (n + SCAN_BS - 1) / SCAN_BS;

    // --- CSR build ---
    lgcn_zero_cnt<<<(n + TPB - 1) / TPB, TPB>>>(n);
    lgcn_hist<<<(n_edges + TPB - 1) / TPB, TPB>>>(edge_row, n_edges);
    lgcn_scan_blocks<<<nb, SCAN_BS>>>(n);
    lgcn_scan_sums<<<1, SCAN_BS>>>(nb);
    lgcn_scan_add<<<(n + TPB - 1) / TPB, TPB>>>(n, n_edges);
    lgcn_scatter<<<(n_edges + TPB - 1) / TPB, TPB>>>(edge_row, edge_col, edge_val, n_edges);

    // --- layer 0 init ---
    {
        int total = n * (D / 4);
        lgcn_init_kernel<<<(total + TPB - 1) / TPB, TPB>>>(user_emb, item_emb, embs,
                                                           n_users, n);
    }

    // --- 3 SpMM layers (CSR gather-reduce, no atomics) ---
    {
        long long threads = (long long)n * 32;
        int grid = (int)((threads + TPB - 1) / TPB);
        for (int l = 1; l <= 3; ++l) {
            lgcn_spmm_csr<<<grid, TPB>>>(embs + (size_t)(l - 1) * D,
                                         embs + (size_t)l * D,
                                         n);
        }
    }

    // --- mean over layers ---
    {
        int total = n * (D / 4);
        lgcn_mean_kernel<<<(total + TPB - 1) / TPB, TPB>>>(embs, users, items,
                                                           n_users, n);
    }
}